// round 3
// baseline (speedup 1.0000x reference)
#include <cuda_runtime.h>
#include <cuda_bf16.h>
#include <cstdint>

#define N_NODES   100000
#define DIM       128
#define NEG       5
#define LR        0.025f
#define NCE_BIAS      11.512925464970229f   // log(100000)
#define NCE_NEG_BIAS  9.9034875525361272f   // log(100000/5)
#define LUT_SIZE  1202

// bf16 gather table. Phase 1 (pos): holds bf16(W original).
// Phase 2 (neg): overwritten with bf16(post-positive out).
__device__ __nv_bfloat16 g_snap[(size_t)N_NODES * DIM];

// ---------------------------------------------------------------------------
// helpers
// ---------------------------------------------------------------------------
__device__ __forceinline__ void red4(float* addr, float x, float y, float z, float w) {
    asm volatile("red.global.add.v4.f32 [%0], {%1, %2, %3, %4};"
                 :: "l"(addr), "f"(x), "f"(y), "f"(z), "f"(w)
                 : "memory");
}

__device__ __forceinline__ float lut_sigmoid(float s, const float* __restrict__ lut) {
    s = fminf(fmaxf(s, -6.0f), 6.0f);
    int idx = (int)floorf(__fdiv_rn(s + 6.01f, 0.01f));
    idx = max(0, min(idx, LUT_SIZE - 1));
    return __ldg(lut + idx);
}

__device__ __forceinline__ uint4 pack8_bf16(float4 a, float4 b) {
    __nv_bfloat162 p0 = __floats2bfloat162_rn(a.x, a.y);
    __nv_bfloat162 p1 = __floats2bfloat162_rn(a.z, a.w);
    __nv_bfloat162 p2 = __floats2bfloat162_rn(b.x, b.y);
    __nv_bfloat162 p3 = __floats2bfloat162_rn(b.z, b.w);
    uint4 o;
    o.x = *reinterpret_cast<uint32_t*>(&p0);
    o.y = *reinterpret_cast<uint32_t*>(&p1);
    o.z = *reinterpret_cast<uint32_t*>(&p2);
    o.w = *reinterpret_cast<uint32_t*>(&p3);
    return o;
}

__device__ __forceinline__ void unpack4_bf16(uint2 r, float* f) {
    float2 lo = __bfloat1622float2(*reinterpret_cast<__nv_bfloat162*>(&r.x));
    float2 hi = __bfloat1622float2(*reinterpret_cast<__nv_bfloat162*>(&r.y));
    f[0] = lo.x; f[1] = lo.y; f[2] = hi.x; f[3] = hi.y;
}

// ---------------------------------------------------------------------------
// K0: one pass over W -> out (fp32 copy) + g_snap (bf16). 8 floats/thread.
// ---------------------------------------------------------------------------
__global__ void __launch_bounds__(256)
init_kernel(const float4* __restrict__ W, float4* __restrict__ out, int n8) {
    int i = blockIdx.x * blockDim.x + threadIdx.x;
    if (i >= n8) return;
    float4 a = __ldg(W + 2 * i);
    float4 b = __ldg(W + 2 * i + 1);
    out[2 * i]     = a;
    out[2 * i + 1] = b;
    reinterpret_cast<uint4*>(g_snap)[i] = pack8_bf16(a, b);
}

// K2: g_snap = bf16(out) (post-positive table)
__global__ void __launch_bounds__(256)
snapshot_kernel(const float4* __restrict__ src, int n8) {
    int i = blockIdx.x * blockDim.x + threadIdx.x;
    if (i >= n8) return;
    float4 a = __ldg(src + 2 * i);
    float4 b = __ldg(src + 2 * i + 1);
    reinterpret_cast<uint4*>(g_snap)[i] = pack8_bf16(a, b);
}

// ---------------------------------------------------------------------------
// K1: positive pairs. One warp per pair. Gathers read bf16(original W) from
// g_snap (L2-resident, 26 MB); reds go to d_out fp32.
// ---------------------------------------------------------------------------
__global__ void __launch_bounds__(256)
pos_kernel(const float* __restrict__ lut,
           const int*   __restrict__ iu,
           const int*   __restrict__ iv,
           float*       __restrict__ out,
           int n_pairs) {
    int warp = (blockIdx.x * blockDim.x + threadIdx.x) >> 5;
    int lane = threadIdx.x & 31;
    if (warp >= n_pairs) return;

    const uint2* snap = reinterpret_cast<const uint2*>(g_snap);
    int u = __ldg(iu + warp);
    int v = __ldg(iv + warp);

    uint2 ra = __ldg(snap + u * 32 + lane);   // 32 = DIM*2B / 8B
    uint2 rb = __ldg(snap + v * 32 + lane);

    float a[4], b[4];
    unpack4_bf16(ra, a);
    unpack4_bf16(rb, b);

    float p = a[0] * b[0] + a[1] * b[1] + a[2] * b[2] + a[3] * b[3];
#pragma unroll
    for (int o = 16; o; o >>= 1) p += __shfl_xor_sync(0xffffffffu, p, o);

    float sc = (1.0f - lut_sigmoid(p - NCE_BIAS, lut)) * LR;

    red4(out + u * DIM + lane * 4, sc * b[0], sc * b[1], sc * b[2], sc * b[3]);
    red4(out + v * DIM + lane * 4, sc * a[0], sc * a[1], sc * a[2], sc * a[3]);
}

// ---------------------------------------------------------------------------
// K3: negatives. One warp per group of NEG sharing one u; u-update
// accumulated in registers -> 6 red4-rows per group instead of 10.
// ---------------------------------------------------------------------------
__global__ void __launch_bounds__(256)
neg_kernel(const float* __restrict__ lut,
           const int*   __restrict__ inu,
           const int*   __restrict__ inv,
           float*       __restrict__ out,
           int n_groups) {
    int g    = (blockIdx.x * blockDim.x + threadIdx.x) >> 5;
    int lane = threadIdx.x & 31;
    if (g >= n_groups) return;

    const uint2* snap = reinterpret_cast<const uint2*>(g_snap);

    int u  = __ldg(inu + g * NEG);            // all NEG entries identical
    int vv[NEG];
#pragma unroll
    for (int j = 0; j < NEG; j++) vv[j] = __ldg(inv + g * NEG + j);

    uint2 ru = __ldg(snap + u * 32 + lane);
    uint2 rb[NEG];
#pragma unroll
    for (int j = 0; j < NEG; j++) rb[j] = __ldg(snap + vv[j] * 32 + lane);

    float a[4];
    unpack4_bf16(ru, a);

    float b[NEG][4];
    float p[NEG];
#pragma unroll
    for (int j = 0; j < NEG; j++) {
        unpack4_bf16(rb[j], b[j]);
        p[j] = a[0] * b[j][0] + a[1] * b[j][1] + a[2] * b[j][2] + a[3] * b[j][3];
    }

#pragma unroll
    for (int o = 16; o; o >>= 1) {
#pragma unroll
        for (int j = 0; j < NEG; j++)
            p[j] += __shfl_xor_sync(0xffffffffu, p[j], o);
    }

    float sc[NEG];
#pragma unroll
    for (int j = 0; j < NEG; j++)
        sc[j] = -lut_sigmoid(p[j] - NCE_NEG_BIAS, lut) * LR;

    float du0 = 0.f, du1 = 0.f, du2 = 0.f, du3 = 0.f;
#pragma unroll
    for (int j = 0; j < NEG; j++) {
        du0 += sc[j] * b[j][0];
        du1 += sc[j] * b[j][1];
        du2 += sc[j] * b[j][2];
        du3 += sc[j] * b[j][3];
    }

#pragma unroll
    for (int j = 0; j < NEG; j++)
        red4(out + vv[j] * DIM + lane * 4,
             sc[j] * a[0], sc[j] * a[1], sc[j] * a[2], sc[j] * a[3]);
    red4(out + u * DIM + lane * 4, du0, du1, du2, du3);
}

// ---------------------------------------------------------------------------
// launch
// ---------------------------------------------------------------------------
extern "C" void kernel_launch(void* const* d_in, const int* in_sizes, int n_in,
                              void* d_out, int out_size) {
    const float* W    = (const float*)d_in[0];
    const float* lut  = (const float*)d_in[1];
    const int*   ipu  = (const int*)d_in[2];
    const int*   ipv  = (const int*)d_in[3];
    const int*   inu  = (const int*)d_in[4];
    const int*   inv  = (const int*)d_in[5];
    float*       out  = (float*)d_out;

    const int n_pos   = in_sizes[2];          // 100000
    const int n_neg   = in_sizes[4];          // 500000
    const int n_group = n_neg / NEG;          // 100000
    const int n8      = out_size / 8;         // 1,600,000

    const int CT = 256;

    // K0: out = W (fp32) AND g_snap = bf16(W), one pass
    init_kernel<<<(n8 + CT - 1) / CT, CT>>>((const float4*)W, (float4*)out, n8);
    // K1: positive scatter (gathers bf16 original W)
    pos_kernel<<<(n_pos * 32 + CT - 1) / CT, CT>>>(lut, ipu, ipv, out, n_pos);
    // K2: refresh snapshot with post-positive table
    snapshot_kernel<<<(n8 + CT - 1) / CT, CT>>>((const float4*)out, n8);
    // K3: negative scatter (gathers bf16 snapshot)
    neg_kernel<<<(n_group * 32 + CT - 1) / CT, CT>>>(lut, inu, inv, out, n_group);
}

// round 4
// speedup vs baseline: 1.0003x; 1.0003x over previous
#include <cuda_runtime.h>
#include <cuda_bf16.h>
#include <cstdint>

#define N_NODES   100000
#define DIM       128
#define NEG       5
#define LR        0.025f
#define NCE_BIAS      11.512925464970229f   // log(100000)
#define NCE_NEG_BIAS  9.9034875525361272f   // log(100000/5)
#define LUT_SIZE  1202

// bf16 mirror of the evolving table. init: bf16(W). pos keeps it current via
// bf16 atomics, so when neg starts it holds bf16(post-positive table).
__device__ __nv_bfloat16 g_snap[(size_t)N_NODES * DIM];

// ---------------------------------------------------------------------------
// helpers
// ---------------------------------------------------------------------------
__device__ __forceinline__ void red4(float* addr, float x, float y, float z, float w) {
    asm volatile("red.global.add.v4.f32 [%0], {%1, %2, %3, %4};"
                 :: "l"(addr), "f"(x), "f"(y), "f"(z), "f"(w)
                 : "memory");
}

// two packed bf16x2 atomic adds (8 bytes = this lane's 4-element slice)
__device__ __forceinline__ void red_bf16x4(__nv_bfloat16* addr,
                                           float x, float y, float z, float w) {
    __nv_bfloat162 lo = __floats2bfloat162_rn(x, y);
    __nv_bfloat162 hi = __floats2bfloat162_rn(z, w);
    uint32_t l = *reinterpret_cast<uint32_t*>(&lo);
    uint32_t h = *reinterpret_cast<uint32_t*>(&hi);
    asm volatile("red.global.add.noftz.bf16x2 [%0], %1;"
                 :: "l"(addr), "r"(l) : "memory");
    asm volatile("red.global.add.noftz.bf16x2 [%0], %1;"
                 :: "l"(addr + 2), "r"(h) : "memory");
}

__device__ __forceinline__ float lut_sigmoid(float s, const float* __restrict__ lut) {
    s = fminf(fmaxf(s, -6.0f), 6.0f);
    int idx = (int)floorf(__fdiv_rn(s + 6.01f, 0.01f));
    idx = max(0, min(idx, LUT_SIZE - 1));
    return __ldg(lut + idx);
}

__device__ __forceinline__ void unpack4(uint2 r, float f[4]) {
    float2 lo = __bfloat1622float2(*reinterpret_cast<__nv_bfloat162*>(&r.x));
    float2 hi = __bfloat1622float2(*reinterpret_cast<__nv_bfloat162*>(&r.y));
    f[0] = lo.x; f[1] = lo.y; f[2] = hi.x; f[3] = hi.y;
}

__device__ __forceinline__ float dot4_packed(const float a[4], uint2 r) {
    float2 lo = __bfloat1622float2(*reinterpret_cast<__nv_bfloat162*>(&r.x));
    float2 hi = __bfloat1622float2(*reinterpret_cast<__nv_bfloat162*>(&r.y));
    return a[0] * lo.x + a[1] * lo.y + a[2] * hi.x + a[3] * hi.y;
}

// ---------------------------------------------------------------------------
// K0: one pass over W -> out (fp32 copy) + g_snap (bf16). 8 floats/thread.
// ---------------------------------------------------------------------------
__global__ void __launch_bounds__(256)
init_kernel(const float4* __restrict__ W, float4* __restrict__ out, int n8) {
    int i = blockIdx.x * blockDim.x + threadIdx.x;
    if (i >= n8) return;
    float4 a = __ldg(W + 2 * i);
    float4 b = __ldg(W + 2 * i + 1);
    out[2 * i]     = a;
    out[2 * i + 1] = b;
    __nv_bfloat162 p0 = __floats2bfloat162_rn(a.x, a.y);
    __nv_bfloat162 p1 = __floats2bfloat162_rn(a.z, a.w);
    __nv_bfloat162 p2 = __floats2bfloat162_rn(b.x, b.y);
    __nv_bfloat162 p3 = __floats2bfloat162_rn(b.z, b.w);
    uint4 o;
    o.x = *reinterpret_cast<uint32_t*>(&p0);
    o.y = *reinterpret_cast<uint32_t*>(&p1);
    o.z = *reinterpret_cast<uint32_t*>(&p2);
    o.w = *reinterpret_cast<uint32_t*>(&p3);
    reinterpret_cast<uint4*>(g_snap)[i] = o;
}

// ---------------------------------------------------------------------------
// K1: positive pairs. One warp per pair. Gathers bf16(W original) from
// g_snap; fp32 reds into out AND bf16 reds into g_snap (keeps mirror live).
// ---------------------------------------------------------------------------
__global__ void __launch_bounds__(256)
pos_kernel(const float* __restrict__ lut,
           const int*   __restrict__ iu,
           const int*   __restrict__ iv,
           float*       __restrict__ out,
           int n_pairs) {
    int warp = (blockIdx.x * blockDim.x + threadIdx.x) >> 5;
    int lane = threadIdx.x & 31;
    if (warp >= n_pairs) return;

    const uint2* snap = reinterpret_cast<const uint2*>(g_snap);
    int u = __ldg(iu + warp);
    int v = __ldg(iv + warp);

    uint2 ra = __ldg(snap + u * 32 + lane);   // 32 uint2 per 128-elem row
    uint2 rb = __ldg(snap + v * 32 + lane);

    float a[4], b[4];
    unpack4(ra, a);
    unpack4(rb, b);

    float p = a[0] * b[0] + a[1] * b[1] + a[2] * b[2] + a[3] * b[3];
#pragma unroll
    for (int o = 16; o; o >>= 1) p += __shfl_xor_sync(0xffffffffu, p, o);

    float sc = (1.0f - lut_sigmoid(p - NCE_BIAS, lut)) * LR;

    float ux = sc * b[0], uy = sc * b[1], uz = sc * b[2], uw = sc * b[3];
    float vx = sc * a[0], vy = sc * a[1], vz = sc * a[2], vw = sc * a[3];

    red4(out + u * DIM + lane * 4, ux, uy, uz, uw);
    red4(out + v * DIM + lane * 4, vx, vy, vz, vw);
    red_bf16x4(g_snap + u * DIM + lane * 4, ux, uy, uz, uw);
    red_bf16x4(g_snap + v * DIM + lane * 4, vx, vy, vz, vw);
}

// ---------------------------------------------------------------------------
// K3: negatives. One warp per group of NEG sharing one u. Gathers from the
// live bf16 mirror (== post-positive table); fp32 reds into out.
// b rows stay packed in registers; unpacked on the fly (reg diet -> occ up).
// ---------------------------------------------------------------------------
__global__ void __launch_bounds__(256)
neg_kernel(const float* __restrict__ lut,
           const int*   __restrict__ inu,
           const int*   __restrict__ inv,
           float*       __restrict__ out,
           int n_groups) {
    int g    = (blockIdx.x * blockDim.x + threadIdx.x) >> 5;
    int lane = threadIdx.x & 31;
    if (g >= n_groups) return;

    const uint2* snap = reinterpret_cast<const uint2*>(g_snap);

    int u = __ldg(inu + g * NEG);             // all NEG entries identical
    int vv[NEG];
#pragma unroll
    for (int j = 0; j < NEG; j++) vv[j] = __ldg(inv + g * NEG + j);

    uint2 ru = __ldg(snap + u * 32 + lane);
    uint2 rb[NEG];
#pragma unroll
    for (int j = 0; j < NEG; j++) rb[j] = __ldg(snap + vv[j] * 32 + lane);

    float a[4];
    unpack4(ru, a);

    float p[NEG];
#pragma unroll
    for (int j = 0; j < NEG; j++) p[j] = dot4_packed(a, rb[j]);

#pragma unroll
    for (int o = 16; o; o >>= 1) {
#pragma unroll
        for (int j = 0; j < NEG; j++)
            p[j] += __shfl_xor_sync(0xffffffffu, p[j], o);
    }

    float sc[NEG];
#pragma unroll
    for (int j = 0; j < NEG; j++)
        sc[j] = -lut_sigmoid(p[j] - NCE_NEG_BIAS, lut) * LR;

    float du0 = 0.f, du1 = 0.f, du2 = 0.f, du3 = 0.f;
#pragma unroll
    for (int j = 0; j < NEG; j++) {
        float b[4];
        unpack4(rb[j], b);
        du0 += sc[j] * b[0];
        du1 += sc[j] * b[1];
        du2 += sc[j] * b[2];
        du3 += sc[j] * b[3];
        red4(out + vv[j] * DIM + lane * 4,
             sc[j] * a[0], sc[j] * a[1], sc[j] * a[2], sc[j] * a[3]);
    }
    red4(out + u * DIM + lane * 4, du0, du1, du2, du3);
}

// ---------------------------------------------------------------------------
// launch
// ---------------------------------------------------------------------------
extern "C" void kernel_launch(void* const* d_in, const int* in_sizes, int n_in,
                              void* d_out, int out_size) {
    const float* W    = (const float*)d_in[0];
    const float* lut  = (const float*)d_in[1];
    const int*   ipu  = (const int*)d_in[2];
    const int*   ipv  = (const int*)d_in[3];
    const int*   inu  = (const int*)d_in[4];
    const int*   inv  = (const int*)d_in[5];
    float*       out  = (float*)d_out;

    const int n_pos   = in_sizes[2];          // 100000
    const int n_neg   = in_sizes[4];          // 500000
    const int n_group = n_neg / NEG;          // 100000
    const int n8      = out_size / 8;         // 1,600,000

    const int CT = 256;

    // K0: out = W (fp32) AND g_snap = bf16(W)
    init_kernel<<<(n8 + CT - 1) / CT, CT>>>((const float4*)W, (float4*)out, n8);
    // K1: positive scatter; keeps g_snap in sync via bf16 atomics
    pos_kernel<<<(n_pos * 32 + CT - 1) / CT, CT>>>(lut, ipu, ipv, out, n_pos);
    // K3: negative scatter (gathers live bf16 mirror) — no snapshot pass needed
    neg_kernel<<<(n_group * 32 + CT - 1) / CT, CT>>>(lut, inu, inv, out, n_group);
}